// round 17
// baseline (speedup 1.0000x reference)
#include <cuda_runtime.h>
#include <cuda_fp16.h>
#include <cstdint>

#define HN       128
#define BATCH    1024
#define SEQT     512
#define CL       2            // CTAs per cluster
#define MROWS    16           // batch rows per cluster
#define NTHREADS 256

#define SAW      132          // A-tile row stride in 32-bit words (264 fp16 = 528 B)
#define AWORDS   (MROWS * SAW)           // 2112 words per A buffer
#define ABYTES   (AWORDS * 4)            // 8448 B

// ---- shared memory layout (32-bit word offsets) ----
#define OF_A     0                       // A tiles x2 (parity) = 4224 words
#define OF_B1    (2 * AWORDS)            // layer-1 B frags: 16384 words (64 KB)
#define OF_B2    (OF_B1 + 16384)         // layer-2 B frags: 32768 words (128 KB)
#define OF_WX    (OF_B2 + 32768)         // Wih1 slice   [256] floats (4 gates x 64 dims)
#define OF_BB1   (OF_WX + 256)           // bih1+bhh1    [256] floats
#define OF_BB2   (OF_BB1 + 256)          // bih2+bhh2    [256] floats
#define OF_P     (OF_BB2 + 256)          // layer-2 partial (fp16x2): 16 x 128 words = 8 KB
#define OF_MB    (OF_P + 2048)           // exchange mbarrier (u64)
#define SMEM_WORDS (OF_MB + 2)
#define SMEM_BYTES (SMEM_WORDS * 4)      // 224,776 B

// ---- device scratch (allocation-free) ----
__device__ float g_xT[SEQT * BATCH];     // x transposed to [T, B]

// ======================= helpers =======================
__device__ __forceinline__ uint32_t smem_u32(const void* p) {
    uint32_t a;
    asm("{ .reg .u64 t; cvta.to.shared.u64 t, %1; cvt.u32.u64 %0, t; }" : "=r"(a) : "l"(p));
    return a;
}
__device__ __forceinline__ uint32_t mapa_u32(uint32_t addr, int r) {
    uint32_t o;
    asm("mapa.shared::cluster.u32 %0, %1, %2;" : "=r"(o) : "r"(addr), "r"(r));
    return o;
}
#define CLUSTER_ARRIVE() asm volatile("barrier.cluster.arrive.aligned;" ::: "memory")
#define CLUSTER_WAIT()   asm volatile("barrier.cluster.wait.aligned;" ::: "memory")
#define STSC(addr, v)    asm volatile("st.shared::cluster.u32 [%0], %1;" :: "r"(addr), "r"(v) : "memory")
#define STSL(addr, v)    asm volatile("st.shared.u32 [%0], %1;" :: "r"(addr), "r"(v) : "memory")
#define BAR_ARRIVE(id)   asm volatile("bar.arrive %0, %1;" :: "r"(id), "r"(256) : "memory")
#define BAR_SYNC(id)     asm volatile("bar.sync %0, %1;"   :: "r"(id), "r"(256) : "memory")

#define MBAR_INIT(mb, n) asm volatile("mbarrier.init.shared.b64 [%0], %1;" :: "r"(mb), "r"(n) : "memory")
#define MBAR_ARRIVE_LOCAL(mb) \
    asm volatile("mbarrier.arrive.shared.b64 _, [%0];" :: "r"(mb) : "memory")
#define MBAR_ARRIVE_REMOTE(mb) \
    asm volatile("mbarrier.arrive.release.cluster.shared::cluster.b64 _, [%0];" :: "r"(mb) : "memory")

__device__ __forceinline__ void mbar_wait_cluster(uint32_t mb, uint32_t parity) {
    asm volatile(
        "{\n\t.reg .pred P;\n\t"
        "LAB_%=:\n\t"
        "mbarrier.try_wait.parity.acquire.cluster.shared::cta.b64 P, [%0], %1, 0x989680;\n\t"
        "@P bra.uni DONE_%=;\n\t"
        "bra.uni LAB_%=;\n\t"
        "DONE_%=:\n\t}"
        :: "r"(mb), "r"(parity) : "memory");
}

__device__ __forceinline__ void mmaf16(float* d, const uint32_t* a, uint32_t b0, uint32_t b1) {
    asm volatile(
        "mma.sync.aligned.m16n8k16.row.col.f32.f16.f16.f32 "
        "{%0,%1,%2,%3}, {%4,%5,%6,%7}, {%8,%9}, {%0,%1,%2,%3};"
        : "+f"(d[0]), "+f"(d[1]), "+f"(d[2]), "+f"(d[3])
        : "r"(a[0]), "r"(a[1]), "r"(a[2]), "r"(a[3]), "r"(b0), "r"(b1));
}
__device__ __forceinline__ void ldmA(uint32_t* r, uint32_t addr) {
    asm volatile("ldmatrix.sync.aligned.m8n8.x4.shared.b16 {%0,%1,%2,%3}, [%4];"
                 : "=r"(r[0]), "=r"(r[1]), "=r"(r[2]), "=r"(r[3]) : "r"(addr));
}
// full-approx activations (validated: rel_err 4.70e-4)
__device__ __forceinline__ float tanha(float x) {
    float y; asm("tanh.approx.f32 %0, %1;" : "=f"(y) : "f"(x)); return y;
}
__device__ __forceinline__ float sigfa(float x) {
    return fmaf(0.5f, tanha(0.5f * x), 0.5f);
}

// ======================= kernels =======================
__global__ void xT_kernel(const float* __restrict__ x) {
    int i = blockIdx.x * blockDim.x + threadIdx.x;   // i = t*1024 + b (coalesced writes)
    if (i < BATCH * SEQT) {
        int tt = i >> 10, b = i & 1023;
        g_xT[i] = x[b * SEQT + tt];
    }
}

extern "C" __global__ void __launch_bounds__(NTHREADS, 1) __cluster_dims__(CL, 1, 1)
lstm2_kernel(const float* __restrict__ Wih1, const float* __restrict__ Whh1,
             const float* __restrict__ bih1, const float* __restrict__ bhh1,
             const float* __restrict__ Wih2, const float* __restrict__ Whh2,
             const float* __restrict__ bih2, const float* __restrict__ bhh2,
             const float* __restrict__ Wl,   const float* __restrict__ bl,
             float* __restrict__ out)
{
    extern __shared__ uint32_t sm[];
    const int tid  = threadIdx.x;
    const int lane = tid & 31;
    const int wid  = tid >> 5;          // 0..7
    const int wg   = wid >> 2;          // 0 = layer-1 (+L2 partial), 1 = layer-2 group
    const int lwid = wid & 3;           // warp within group -> 16-dim slice
    const int g    = lane >> 2;
    const int tq   = lane & 3;
    const int rank = blockIdx.x & (CL - 1);
    const int b0   = (blockIdx.x / CL) * MROWS;

    float* WX  = (float*)(sm + OF_WX);
    float* BB1 = (float*)(sm + OF_BB1);
    float* BB2 = (float*)(sm + OF_BB2);

    // ---- pack weight slices into fp16 mma-fragment order (same as R16) ----
    for (int idx = tid; idx < 16384; idx += NTHREADS) {         // layer 1 (K=128, KTP=8)
        int j = idx & 3, ln = (idx >> 2) & 31, p = (idx >> 7) & 1;
        int ktp = (idx >> 8) & 7, q2 = (idx >> 11) & 1, w = idx >> 12;
        int gate = p * 2 + (j >> 1), reg = j & 1;
        int k0 = ktp * 16 + reg * 8 + 2 * (ln & 3);
        int dim = w * 16 + q2 * 8 + (ln >> 2);
        int gr = gate * HN + rank * 64 + dim;
        __half2 hv = __floats2half2_rn(Whh1[gr * HN + k0], Whh1[gr * HN + k0 + 1]);
        sm[OF_B1 + idx] = *(uint32_t*)&hv;
    }
    for (int idx = tid; idx < 32768; idx += NTHREADS) {         // layer 2 (K=256, KTP=16)
        int j = idx & 3, ln = (idx >> 2) & 31, p = (idx >> 7) & 1;
        int ktp = (idx >> 8) & 15, q2 = (idx >> 12) & 1, w = idx >> 13;
        int gate = p * 2 + (j >> 1), reg = j & 1;
        int k0 = ktp * 16 + reg * 8 + 2 * (ln & 3);
        int dim = w * 16 + q2 * 8 + (ln >> 2);
        int gr = gate * HN + rank * 64 + dim;
        float w0 = (k0 < HN)     ? Wih2[gr * HN + k0]     : Whh2[gr * HN + k0 - HN];
        float w1 = (k0 + 1 < HN) ? Wih2[gr * HN + k0 + 1] : Whh2[gr * HN + k0 + 1 - HN];
        __half2 hv = __floats2half2_rn(w0, w1);
        sm[OF_B2 + idx] = *(uint32_t*)&hv;
    }
    {   // WX / biases: 4 gates x 64 dims
        int gt = tid >> 6, q = tid & 63;
        int gr = gt * HN + rank * 64 + q;
        WX[tid]  = Wih1[gr];
        BB1[tid] = bih1[gr] + bhh1[gr];
        BB2[tid] = bih2[gr] + bhh2[gr];
    }
    for (int i = tid; i < 2 * AWORDS; i += NTHREADS) sm[OF_A + i] = 0u;   // both parities zero
    if (tid == 0) MBAR_INIT(smem_u32(sm) + OF_MB * 4, 2 * NTHREADS);      // 256 local + 256 remote
    __syncthreads();
    // publish zeroed A-tiles + weights + mbarrier before any peer DSMEM write/arrive
    CLUSTER_ARRIVE();
    CLUSTER_WAIT();

    // per-thread rows (2) and ldmatrix offset (single M16 tile)
    int rows[2];
    rows[0] = g;
    rows[1] = g + 8;

    const uint32_t sbA = smem_u32(sm) + OF_A * 4;
    const uint32_t lmoff = (uint32_t)(lane & 15) * 528u + ((lane >> 4) & 1) * 16u;
    const uint32_t mbLocal = smem_u32(sm) + OF_MB * 4;
    const uint32_t mbPeer  = mapa_u32(mbLocal, rank ^ 1);
    // DSMEM write base: peer CTA's A-tile only (local goes via plain STS)
    const uint32_t dstPeer = mapa_u32(sbA, rank ^ 1);

    const uint4* Bq1 = (const uint4*)(sm + OF_B1);
    const uint4* Bq2 = (const uint4*)(sm + OF_B2);

    // ---- hoist loop-invariant B fragments into registers ----
    uint4 bh[32];
    if (wg == 0) {
#pragma unroll
        for (int ktp = 0; ktp < 8; ktp++) {
            int base = (lwid * 2) * 8 + ktp;
            bh[ktp * 4 + 0] = Bq1[((base) * 2 + 0) * 32 + lane];
            bh[ktp * 4 + 1] = Bq1[((base) * 2 + 1) * 32 + lane];
            bh[ktp * 4 + 2] = Bq1[((base + 8) * 2 + 0) * 32 + lane];
            bh[ktp * 4 + 3] = Bq1[((base + 8) * 2 + 1) * 32 + lane];
        }
    } else {
#pragma unroll
        for (int ktp = 0; ktp < 8; ktp++) {
            int base = (lwid * 2) * 16 + ktp;
            bh[ktp * 4 + 0] = Bq2[((base) * 2 + 0) * 32 + lane];
            bh[ktp * 4 + 1] = Bq2[((base) * 2 + 1) * 32 + lane];
            bh[ktp * 4 + 2] = Bq2[((base + 16) * 2 + 0) * 32 + lane];
            bh[ktp * 4 + 3] = Bq2[((base + 16) * 2 + 1) * 32 + lane];
        }
    }
    // ---- hoist epilogue constants (per-thread slice of WX / biases) ----
    float wxv[16], bbv[16];
    {
        const float* Bt = (wg == 0) ? BB1 : BB2;
#pragma unroll
        for (int gate = 0; gate < 4; gate++)
#pragma unroll
            for (int q2 = 0; q2 < 2; q2++)
#pragma unroll
                for (int qq = 0; qq < 2; qq++) {
                    int qloc = lwid * 16 + q2 * 8 + tq * 2 + qq;
                    int ii = gate * 4 + q2 * 2 + qq;
                    bbv[ii] = Bt[gate * 64 + qloc];
                    wxv[ii] = (wg == 0) ? WX[gate * 64 + qloc] : 0.f;
                }
    }

    // WG0 carries c1, WG1 carries c2: 8 cells (2 rows x 2 q2 x 2 qq)
    float cc[8];
#pragma unroll
    for (int i = 0; i < 8; i++) cc[i] = 0.f;

    // write word-column (within 128-word row): h1 -> +0, h2 -> +64
    const int wcol = rank * 32 + lwid * 8 + tq;    // + q2*4 added in loop

    // initial x prefetch (t=0)
    float xtv[2];
    if (wg == 0) {
#pragma unroll
        for (int e = 0; e < 2; e++) xtv[e] = __ldcg(&g_xT[0 * BATCH + b0 + rows[e]]);
    } else {
        // prime WAR barrier (id 2): WG0's first bar.sync(2) consumes this
        BAR_ARRIVE(2);
    }

    for (int n = 0; n <= SEQT; n++) {
        const uint32_t rbase = sbA + (uint32_t)(n & 1) * ABYTES;         // read parity
        const uint32_t wpar  = (uint32_t)((n + 1) & 1) * ABYTES;         // write parity offset

        // wait for phase n-1 (all 512 arrives of previous iteration)
        if (n > 0) mbar_wait_cluster(mbLocal, (n - 1) & 1);

        if (wg == 0) {
            // ---- layer-2 partial: ktp 12..15 (computed first, handed to WG1) ----
            BAR_SYNC(2);     // WG1 finished reading previous partial
            {
                float acc[4][2][4];
#pragma unroll
                for (int a1 = 0; a1 < 4; a1++)
#pragma unroll
                    for (int a2 = 0; a2 < 2; a2++)
#pragma unroll
                        for (int a3 = 0; a3 < 4; a3++) acc[a1][a2][a3] = 0.f;
#pragma unroll
                for (int ktp = 12; ktp < 16; ktp++) {
                    int base = (lwid * 2) * 16 + ktp;
                    uint4 b0v = Bq2[((base) * 2 + 0) * 32 + lane];
                    uint4 b1v = Bq2[((base) * 2 + 1) * 32 + lane];
                    uint4 b2v = Bq2[((base + 16) * 2 + 0) * 32 + lane];
                    uint4 b3v = Bq2[((base + 16) * 2 + 1) * 32 + lane];
                    uint32_t af[4];
                    ldmA(af, rbase + lmoff + ktp * 32u);
                    mmaf16(acc[0][0], af, b0v.x, b0v.y);
                    mmaf16(acc[1][0], af, b0v.z, b0v.w);
                    mmaf16(acc[2][0], af, b1v.x, b1v.y);
                    mmaf16(acc[3][0], af, b1v.z, b1v.w);
                    mmaf16(acc[0][1], af, b2v.x, b2v.y);
                    mmaf16(acc[1][1], af, b2v.z, b2v.w);
                    mmaf16(acc[2][1], af, b3v.x, b3v.y);
                    mmaf16(acc[3][1], af, b3v.z, b3v.w);
                }
                // store partial as fp16x2, layout [idx][tid] (conflict-free)
#pragma unroll
                for (int gate = 0; gate < 4; gate++)
#pragma unroll
                    for (int q2 = 0; q2 < 2; q2++)
#pragma unroll
                        for (int e = 0; e < 2; e++) {
                            __half2 hp = __floats2half2_rn(acc[gate][q2][e * 2 + 0],
                                                           acc[gate][q2][e * 2 + 1]);
                            sm[OF_P + (gate * 4 + q2 * 2 + e) * 128 + tid] = *(uint32_t*)&hp;
                        }
            }
            BAR_ARRIVE(1);   // partial ready for WG1

            // ===== layer 1: gates1(t=n) = h1(n-1) @ Whh1^T =====
            if (n < SEQT) {
                float acc[4][2][4];
#pragma unroll
                for (int a1 = 0; a1 < 4; a1++)
#pragma unroll
                    for (int a2 = 0; a2 < 2; a2++)
#pragma unroll
                        for (int a3 = 0; a3 < 4; a3++) acc[a1][a2][a3] = 0.f;
#pragma unroll
                for (int ktp = 0; ktp < 8; ktp++) {
                    uint32_t af[4];
                    ldmA(af, rbase + lmoff + ktp * 32u);
                    mmaf16(acc[0][0], af, bh[ktp * 4 + 0].x, bh[ktp * 4 + 0].y);
                    mmaf16(acc[1][0], af, bh[ktp * 4 + 0].z, bh[ktp * 4 + 0].w);
                    mmaf16(acc[2][0], af, bh[ktp * 4 + 1].x, bh[ktp * 4 + 1].y);
                    mmaf16(acc[3][0], af, bh[ktp * 4 + 1].z, bh[ktp * 4 + 1].w);
                    mmaf16(acc[0][1], af, bh[ktp * 4 + 2].x, bh[ktp * 4 + 2].y);
                    mmaf16(acc[1][1], af, bh[ktp * 4 + 2].z, bh[ktp * 4 + 2].w);
                    mmaf16(acc[2][1], af, bh[ktp * 4 + 3].x, bh[ktp * 4 + 3].y);
                    mmaf16(acc[3][1], af, bh[ktp * 4 + 3].z, bh[ktp * 4 + 3].w);
                }
#pragma unroll
                for (int e = 0; e < 2; e++)
#pragma unroll
                    for (int q2 = 0; q2 < 2; q2++) {
                        float hv[2];
#pragma unroll
                        for (int qq = 0; qq < 2; qq++) {
                            int fr = e * 2 + qq;
                            int ii = q2 * 2 + qq;
                            float gi = acc[0][q2][fr] + xtv[e] * wxv[ii]      + bbv[ii];
                            float gf = acc[1][q2][fr] + xtv[e] * wxv[4 + ii]  + bbv[4 + ii];
                            float gg = acc[2][q2][fr] + xtv[e] * wxv[8 + ii]  + bbv[8 + ii];
                            float go = acc[3][q2][fr] + xtv[e] * wxv[12 + ii] + bbv[12 + ii];
                            float iv = sigfa(gi), fv = sigfa(gf), gv = tanha(gg), ov = sigfa(go);
                            int ci = e * 4 + q2 * 2 + qq;
                            cc[ci] = fv * cc[ci] + iv * gv;
                            hv[qq] = ov * tanha(cc[ci]);
                        }
                        __half2 hp = __floats2half2_rn(hv[0], hv[1]);
                        uint32_t v = *(uint32_t*)&hp;
                        uint32_t boff = wpar + (uint32_t)(rows[e] * SAW + wcol + q2 * 4) * 4u;
                        STSL(sbA + boff, v);
                        STSC(dstPeer + boff, v);
                    }
            }
        } else {
            // ===== layer 2: gates2(t=n-1), ktp 0..11 (WG0 supplies 12..15) =====
            float acc[4][2][4];
            if (n > 0) {
#pragma unroll
                for (int a1 = 0; a1 < 4; a1++)
#pragma unroll
                    for (int a2 = 0; a2 < 2; a2++)
#pragma unroll
                        for (int a3 = 0; a3 < 4; a3++) acc[a1][a2][a3] = 0.f;
                // ktp 0..7 hoisted
#pragma unroll
                for (int ktp = 0; ktp < 8; ktp++) {
                    uint32_t af[4];
                    ldmA(af, rbase + lmoff + ktp * 32u);
                    mmaf16(acc[0][0], af, bh[ktp * 4 + 0].x, bh[ktp * 4 + 0].y);
                    mmaf16(acc[1][0], af, bh[ktp * 4 + 0].z, bh[ktp * 4 + 0].w);
                    mmaf16(acc[2][0], af, bh[ktp * 4 + 1].x, bh[ktp * 4 + 1].y);
                    mmaf16(acc[3][0], af, bh[ktp * 4 + 1].z, bh[ktp * 4 + 1].w);
                    mmaf16(acc[0][1], af, bh[ktp * 4 + 2].x, bh[ktp * 4 + 2].y);
                    mmaf16(acc[1][1], af, bh[ktp * 4 + 2].z, bh[ktp * 4 + 2].w);
                    mmaf16(acc[2][1], af, bh[ktp * 4 + 3].x, bh[ktp * 4 + 3].y);
                    mmaf16(acc[3][1], af, bh[ktp * 4 + 3].z, bh[ktp * 4 + 3].w);
                }
                // ktp 8..11 from smem
#pragma unroll 2
                for (int ktp = 8; ktp < 12; ktp++) {
                    int base = (lwid * 2) * 16 + ktp;
                    uint4 b0v = Bq2[((base) * 2 + 0) * 32 + lane];
                    uint4 b1v = Bq2[((base) * 2 + 1) * 32 + lane];
                    uint4 b2v = Bq2[((base + 16) * 2 + 0) * 32 + lane];
                    uint4 b3v = Bq2[((base + 16) * 2 + 1) * 32 + lane];
                    uint32_t af[4];
                    ldmA(af, rbase + lmoff + ktp * 32u);
                    mmaf16(acc[0][0], af, b0v.x, b0v.y);
                    mmaf16(acc[1][0], af, b0v.z, b0v.w);
                    mmaf16(acc[2][0], af, b1v.x, b1v.y);
                    mmaf16(acc[3][0], af, b1v.z, b1v.w);
                    mmaf16(acc[0][1], af, b2v.x, b2v.y);
                    mmaf16(acc[1][1], af, b2v.z, b2v.w);
                    mmaf16(acc[2][1], af, b3v.x, b3v.y);
                    mmaf16(acc[3][1], af, b3v.z, b3v.w);
                }
            }
            BAR_SYNC(1);     // wait for WG0's partial
            if (n > 0) {
                int pt = tid - 128;
#pragma unroll
                for (int gate = 0; gate < 4; gate++)
#pragma unroll
                    for (int q2 = 0; q2 < 2; q2++)
#pragma unroll
                        for (int e = 0; e < 2; e++) {
                            uint32_t u = sm[OF_P + (gate * 4 + q2 * 2 + e) * 128 + pt];
                            float2 f = __half22float2(*(__half2*)&u);
                            acc[gate][q2][e * 2 + 0] += f.x;
                            acc[gate][q2][e * 2 + 1] += f.y;
                        }
#pragma unroll
                for (int e = 0; e < 2; e++)
#pragma unroll
                    for (int q2 = 0; q2 < 2; q2++) {
                        float hv[2];
#pragma unroll
                        for (int qq = 0; qq < 2; qq++) {
                            int fr = e * 2 + qq;
                            int ii = q2 * 2 + qq;
                            float gi = acc[0][q2][fr] + bbv[ii];
                            float gf = acc[1][q2][fr] + bbv[4 + ii];
                            float gg = acc[2][q2][fr] + bbv[8 + ii];
                            float go = acc[3][q2][fr] + bbv[12 + ii];
                            float iv = sigfa(gi), fv = sigfa(gf), gv = tanha(gg), ov = sigfa(go);
                            int ci = e * 4 + q2 * 2 + qq;
                            cc[ci] = fv * cc[ci] + iv * gv;
                            hv[qq] = ov * tanha(cc[ci]);
                        }
                        __half2 hp = __floats2half2_rn(hv[0], hv[1]);
                        uint32_t v = *(uint32_t*)&hp;
                        uint32_t boff = wpar + (uint32_t)(rows[e] * SAW + 64 + wcol + q2 * 4) * 4u;
                        STSL(sbA + boff, v);
                        STSC(dstPeer + boff, v);
                    }
            }
            BAR_ARRIVE(2);   // done reading partial; WG0 may overwrite next iter
            // n == 0: h2(-1) = 0 already in pre-zeroed buffers
        }

        // phase-n arrives: local (releases STSL) + remote (releases STSC)
        MBAR_ARRIVE_LOCAL(mbLocal);
        MBAR_ARRIVE_REMOTE(mbPeer);
        if (wg == 0 && n + 1 < SEQT) {
#pragma unroll
            for (int e = 0; e < 2; e++) xtv[e] = __ldcg(&g_xT[(n + 1) * BATCH + b0 + rows[e]]);
        }
    }

    // wait for final phase (SEQT): local + peer h2 writes visible
    mbar_wait_cluster(mbLocal, SEQT & 1);

    // ---- final linear: out[b] = h2[b,:] . Wl + bl ----
    // h2(SEQT-1) sits in A buffer parity (SEQT+1)&1, words 64..127 of each row (local smem)
    if (rank == 0 && tid < MROWS) {
        const uint32_t* hr = sm + OF_A + ((SEQT + 1) & 1) * AWORDS + tid * SAW + 64;
        float acc = bl[0];
#pragma unroll 16
        for (int w = 0; w < 64; w++) {
            uint32_t u = hr[w];
            float2 f = __half22float2(*(__half2*)&u);
            acc += f.x * Wl[2 * w] + f.y * Wl[2 * w + 1];
        }
        out[b0 + tid] = acc;
    }
    // keep both CTAs resident until peer reads of DSMEM are impossible
    CLUSTER_ARRIVE();
    CLUSTER_WAIT();
}

// ======================= launch =======================
extern "C" void kernel_launch(void* const* d_in, const int* in_sizes, int n_in,
                              void* d_out, int out_size) {
    const float* x    = (const float*)d_in[0];
    const float* Wih1 = (const float*)d_in[1];
    const float* Whh1 = (const float*)d_in[2];
    const float* bih1 = (const float*)d_in[3];
    const float* bhh1 = (const float*)d_in[4];
    const float* Wih2 = (const float*)d_in[5];
    const float* Whh2 = (const float*)d_in[6];
    const float* bih2 = (const float*)d_in[7];
    const float* bhh2 = (const float*)d_in[8];
    const float* Wl   = (const float*)d_in[9];
    const float* bl   = (const float*)d_in[10];
    float* out = (float*)d_out;

    cudaFuncSetAttribute(lstm2_kernel, cudaFuncAttributeMaxDynamicSharedMemorySize, SMEM_BYTES);

    xT_kernel<<<(BATCH * SEQT + 255) / 256, 256>>>(x);
    lstm2_kernel<<<(BATCH / MROWS) * CL, NTHREADS, SMEM_BYTES>>>(
        Wih1, Whh1, bih1, bhh1, Wih2, Whh2, bih2, bhh2, Wl, bl, out);
}